// round 3
// baseline (speedup 1.0000x reference)
#include <cuda_runtime.h>

#define BB 128
#define CC 3
#define HH 256
#define WW 256
#define SHIFT 32
#define HW (HH*WW)      // 65536
#define CHW (CC*HW)     // 196608
#define BPI 64          // blocks per image (also transform tiles per image)

__device__ float    g_sum[BB];      // zero-init; reset by last done block
__device__ unsigned g_arrive[BB];   // zero-init; reset by last done block
__device__ unsigned g_done[BB];     // zero-init; reset by last done block

// ONE kernel. grid = BB*BPI blocks, 256 threads.
// Phase A: each block reduces 1/64 of its image, atomicAdd to g_sum[b],
//          arrive++. Spin until all 64 sibling blocks arrived.
// Phase B: compute affine coefficients from the now-complete sum, then do the
//          gather+transform for this block's output tile. Streaming stores.
// Cleanup: last block to finish resets the per-image counters (graph-replay
//          determinism: state returns to all-zeros every call).
__global__ void __launch_bounds__(256) augment_kernel(
    const float* __restrict__ imgs,
    const float* __restrict__ br,  const float* __restrict__ sat,
    const float* __restrict__ con, const int* __restrict__ tx,
    const int* __restrict__ ty,    const int* __restrict__ cx,
    const int* __restrict__ cy,    float* __restrict__ out)
{
    int b   = blockIdx.x / BPI;
    int blk = blockIdx.x % BPI;

    // ---------------- Phase A: partial reduction ----------------
    {
        const float4* p = (const float4*)(imgs + (size_t)b * CHW);
        const int per_blk = (CHW / 4) / BPI;          // 768 float4
        int base = blk * per_blk;
        float s = 0.f;
        #pragma unroll
        for (int i = 0; i < 3; i++) {                 // 768 / 256 = 3
            float4 v = p[base + i * 256 + threadIdx.x];
            s += (v.x + v.y) + (v.z + v.w);
        }
        #pragma unroll
        for (int o = 16; o; o >>= 1) s += __shfl_down_sync(0xffffffffu, s, o);
        __shared__ float ss[8];
        if ((threadIdx.x & 31) == 0) ss[threadIdx.x >> 5] = s;
        __syncthreads();
        if (threadIdx.x == 0) {
            float t = 0.f;
            #pragma unroll
            for (int i = 0; i < 8; i++) t += ss[i];
            atomicAdd(&g_sum[b], t);
            __threadfence();
            atomicAdd(&g_arrive[b], 1u);
        }
    }

    // ---------------- Barrier: wait for all 64 siblings ----------------
    __shared__ float sM0;
    if (threadIdx.x == 0) {
        while (*(volatile unsigned*)&g_arrive[b] < BPI) __nanosleep(40);
        __threadfence();
        sM0 = g_sum[b] * (1.0f / (float)CHW);
    }
    __syncthreads();

    // ---------------- Phase B: transform ----------------
    // out = Af*v + Bf*channel_mean + Cf  on valid pixels, else 0
    float a  = sat[b] * 2.0f;
    float k  = con[b] + 0.5f;
    float Af = k * a;
    float Bf = k * (1.0f - a);
    float Cf = (1.0f - k) * sM0 + (br[b] - 0.5f);

    int txs = tx[b] - SHIFT;
    int tys = ty[b] - SHIFT;
    int cxv = cx[b], cyv = cy[b];
    int xlo = max(0, cxv - 64), xhi = min(HH - 1, cxv + 63);
    int ylo = max(0, cyv - 64), yhi = min(WW - 1, cyv + 63);

    int idx4 = blk * 256 + threadIdx.x;               // float4 index in plane
    int h    = idx4 >> 6;                             // 64 float4 per row
    int w0   = (idx4 & 63) << 2;

    int  sh       = h + txs;
    bool rowvalid = (sh >= 0) & (sh < HH);
    bool rowcut   = (h >= xlo) & (h <= xhi);
    int  sh_c     = min(max(sh, 0), HH - 1);          // safe address even when invalid

    const float* src = imgs + (size_t)b * CHW + (size_t)sh_c * WW;

    float o0[4], o1[4], o2[4];
    #pragma unroll
    for (int j = 0; j < 4; j++) {
        int  w  = w0 + j;
        int  sw = w + tys;
        bool valid = rowvalid & (sw >= 0) & (sw < WW)
                   & !(rowcut & (w >= ylo) & (w <= yhi));
        int sw_c = min(max(sw, 0), WW - 1);
        if (valid) {
            float v0 = __ldg(src + sw_c);
            float v1 = __ldg(src + HW + sw_c);
            float v2 = __ldg(src + 2 * HW + sw_c);
            float m  = (v0 + v1 + v2) * (1.0f / 3.0f);
            float bm = fmaf(Bf, m, Cf);
            o0[j] = fmaf(Af, v0, bm);
            o1[j] = fmaf(Af, v1, bm);
            o2[j] = fmaf(Af, v2, bm);
        } else {
            o0[j] = 0.f; o1[j] = 0.f; o2[j] = 0.f;
        }
    }

    float* dst = out + (size_t)b * CHW + (size_t)h * WW + w0;
    __stcs((float4*)(dst),          make_float4(o0[0], o0[1], o0[2], o0[3]));
    __stcs((float4*)(dst + HW),     make_float4(o1[0], o1[1], o1[2], o1[3]));
    __stcs((float4*)(dst + 2 * HW), make_float4(o2[0], o2[1], o2[2], o2[3]));

    // ---------------- Cleanup: reset per-image state ----------------
    __syncthreads();                     // all threads done with sM0 / stores issued
    if (threadIdx.x == 0) {
        __threadfence();
        unsigned d = atomicAdd(&g_done[b], 1u);
        if (d == BPI - 1) {              // last sibling: restore zeros for replay
            g_sum[b]    = 0.f;
            g_arrive[b] = 0u;
            g_done[b]   = 0u;
            __threadfence();
        }
    }
}

extern "C" void kernel_launch(void* const* d_in, const int* in_sizes, int n_in,
                              void* d_out, int out_size)
{
    const float* imgs = (const float*)d_in[0];
    const float* br   = (const float*)d_in[1];
    const float* sat  = (const float*)d_in[2];
    const float* con  = (const float*)d_in[3];
    const int*   tx   = (const int*)d_in[4];
    const int*   ty   = (const int*)d_in[5];
    const int*   cx   = (const int*)d_in[6];
    const int*   cy   = (const int*)d_in[7];
    float*       out  = (float*)d_out;

    augment_kernel<<<BB * BPI, 256>>>(imgs, br, sat, con, tx, ty, cx, cy, out);
}

// round 4
// speedup vs baseline: 1.4571x; 1.4571x over previous
#include <cuda_runtime.h>

#define BB 128
#define CC 3
#define HH 256
#define WW 256
#define SHIFT 32
#define HW (HH*WW)      // 65536
#define CHW (CC*HW)     // 196608
#define RBLKS 32        // partial-sum blocks per image

__device__ float g_part[BB * RBLKS];

// grid = BB*RBLKS blocks, 256 threads. Each block reduces a contiguous chunk
// of one image and writes ONE partial sum (no atomics, no zero pass needed).
__global__ void __launch_bounds__(256) reduce_kernel(const float* __restrict__ imgs) {
    int b   = blockIdx.x / RBLKS;
    int blk = blockIdx.x % RBLKS;
    const float4* p = (const float4*)(imgs + (size_t)b * CHW);
    const int per_blk = (CHW / 4) / RBLKS;   // 1536 float4 per block
    int base = blk * per_blk;
    float s = 0.f;
    #pragma unroll
    for (int i = 0; i < 6; i++) {            // 1536 / 256 = 6, front-batched
        float4 v = p[base + i * 256 + threadIdx.x];
        s += (v.x + v.y) + (v.z + v.w);
    }
    #pragma unroll
    for (int o = 16; o; o >>= 1) s += __shfl_down_sync(0xffffffffu, s, o);
    __shared__ float ss[8];
    if ((threadIdx.x & 31) == 0) ss[threadIdx.x >> 5] = s;
    __syncthreads();
    if (threadIdx.x < 8) {
        s = ss[threadIdx.x];
        #pragma unroll
        for (int o = 4; o; o >>= 1) s += __shfl_down_sync(0xffu, s, o);
        if (threadIdx.x == 0) g_part[blockIdx.x] = s;
    }
}

// grid = BB * 64 blocks, 256 threads. Each thread owns ONE column w=tid across
// 4 consecutive rows, in all 3 channel planes (12 px). All loads AND stores are
// lane-contiguous -> 1 L1 wavefront per instruction (was 4 on the gather side).
// Column shift/validity/cutout-column tests computed once per thread.
// Streaming stores keep the input resident in L2.
__global__ void __launch_bounds__(256) transform_kernel(
    const float* __restrict__ imgs,
    const float* __restrict__ br,  const float* __restrict__ sat,
    const float* __restrict__ con, const int* __restrict__ tx,
    const int* __restrict__ ty,    const int* __restrict__ cx,
    const int* __restrict__ cy,    float* __restrict__ out)
{
    const int blocks_per_b = HH / 4;                  // 64 (4 rows per block)
    int b  = blockIdx.x / blocks_per_b;
    int h0 = (blockIdx.x % blocks_per_b) * 4;
    int w  = threadIdx.x;                             // 0..255

    // One warp sums this image's 32 partials (L2-broadcast hits).
    __shared__ float sM0;
    if (threadIdx.x < 32) {
        float s = g_part[b * RBLKS + threadIdx.x];
        #pragma unroll
        for (int o = 16; o; o >>= 1) s += __shfl_down_sync(0xffffffffu, s, o);
        if (threadIdx.x == 0) sM0 = s * (1.0f / (float)CHW);
    }
    __syncthreads();

    // Per-image affine coefficients: out = Af*v + Bf*channel_mean + Cf
    float a  = sat[b] * 2.0f;
    float k  = con[b] + 0.5f;
    float Af = k * a;
    float Bf = k * (1.0f - a);
    float Cf = (1.0f - k) * sM0 + (br[b] - 0.5f);

    int txs = tx[b] - SHIFT;
    int tys = ty[b] - SHIFT;
    int cxv = cx[b], cyv = cy[b];
    int xlo = max(0, cxv - 64), xhi = min(HH - 1, cxv + 63);
    int ylo = max(0, cyv - 64), yhi = min(WW - 1, cyv + 63);

    // Per-thread (column) quantities, computed once
    int  sw       = w + tys;
    bool colvalid = (sw >= 0) & (sw < WW);
    int  sw_c     = min(max(sw, 0), WW - 1);
    bool wcut     = (w >= ylo) & (w <= yhi);

    const float* srcb = imgs + (size_t)b * CHW + sw_c;

    // Batch all 12 loads (clamped addresses, unconditional) for max MLP
    float v0[4], v1[4], v2[4];
    int   sh_c[4];
    bool  valid[4];
    #pragma unroll
    for (int r = 0; r < 4; r++) {
        int  h  = h0 + r;
        int  sh = h + txs;
        bool rowvalid = (sh >= 0) & (sh < HH);
        valid[r] = colvalid & rowvalid
                 & !(wcut & (h >= xlo) & (h <= xhi));
        sh_c[r] = min(max(sh, 0), HH - 1) * WW;
    }
    #pragma unroll
    for (int r = 0; r < 4; r++) {
        v0[r] = __ldg(srcb + sh_c[r]);
        v1[r] = __ldg(srcb + HW + sh_c[r]);
        v2[r] = __ldg(srcb + 2 * HW + sh_c[r]);
    }

    float* dst = out + (size_t)b * CHW + (size_t)h0 * WW + w;
    #pragma unroll
    for (int r = 0; r < 4; r++) {
        float m  = (v0[r] + v1[r] + v2[r]) * (1.0f / 3.0f);
        float bm = fmaf(Bf, m, Cf);
        float o0 = valid[r] ? fmaf(Af, v0[r], bm) : 0.f;
        float o1 = valid[r] ? fmaf(Af, v1[r], bm) : 0.f;
        float o2 = valid[r] ? fmaf(Af, v2[r], bm) : 0.f;
        __stcs(dst + r * WW,          o0);
        __stcs(dst + HW + r * WW,     o1);
        __stcs(dst + 2 * HW + r * WW, o2);
    }
}

extern "C" void kernel_launch(void* const* d_in, const int* in_sizes, int n_in,
                              void* d_out, int out_size)
{
    const float* imgs = (const float*)d_in[0];
    const float* br   = (const float*)d_in[1];
    const float* sat  = (const float*)d_in[2];
    const float* con  = (const float*)d_in[3];
    const int*   tx   = (const int*)d_in[4];
    const int*   ty   = (const int*)d_in[5];
    const int*   cx   = (const int*)d_in[6];
    const int*   cy   = (const int*)d_in[7];
    float*       out  = (float*)d_out;

    reduce_kernel<<<BB * RBLKS, 256>>>(imgs);
    transform_kernel<<<BB * (HH / 4), 256>>>(imgs, br, sat, con,
                                             tx, ty, cx, cy, out);
}

// round 6
// speedup vs baseline: 1.6494x; 1.1320x over previous
#include <cuda_runtime.h>

#define BB 128
#define HH 256
#define WW 256
#define SHIFT 32
#define HW (HH*WW)      // 65536
#define CHW (3*HW)      // 196608
#define RBLKS 32        // reduce blocks per image
#define BPI 64          // transform blocks per image
#define HALF (BB/2)     // 64 images per chunk

__device__ float g_part[BB * RBLKS];

// ---- reduce role: one block sums 1/32 of one image, writes one partial ----
__device__ __forceinline__ void reduce_role(const float* __restrict__ imgs,
                                            int b, int blk)
{
    const float4* p = (const float4*)(imgs + (size_t)b * CHW);
    const int per_blk = (CHW / 4) / RBLKS;   // 1536 float4
    int base = blk * per_blk;
    float s = 0.f;
    #pragma unroll
    for (int i = 0; i < 6; i++) {            // front-batched, MLP=6/thread
        float4 v = p[base + i * 256 + threadIdx.x];
        s += (v.x + v.y) + (v.z + v.w);
    }
    #pragma unroll
    for (int o = 16; o; o >>= 1) s += __shfl_down_sync(0xffffffffu, s, o);
    __shared__ float ss[8];
    if ((threadIdx.x & 31) == 0) ss[threadIdx.x >> 5] = s;
    __syncthreads();
    if (threadIdx.x < 8) {
        s = ss[threadIdx.x];
        #pragma unroll
        for (int o = 4; o; o >>= 1) s += __shfl_down_sync(0xffu, s, o);
        if (threadIdx.x == 0) g_part[b * RBLKS + blk] = s;
    }
}

// ---- transform role: R2 mapping, one float4 per thread in each of 3 planes ----
__device__ __forceinline__ void transform_role(
    const float* __restrict__ imgs,
    const float* __restrict__ br,  const float* __restrict__ sat,
    const float* __restrict__ con, const int* __restrict__ tx,
    const int* __restrict__ ty,    const int* __restrict__ cx,
    const int* __restrict__ cy,    float* __restrict__ out,
    int b, int blk)
{
    int idx4 = blk * 256 + threadIdx.x;               // float4 index in plane
    int h    = idx4 >> 6;                             // 64 float4 per row
    int w0   = (idx4 & 63) << 2;

    // One warp sums this image's 32 partials (L2-broadcast hits).
    __shared__ float sM0;
    if (threadIdx.x < 32) {
        float s = g_part[b * RBLKS + threadIdx.x];
        #pragma unroll
        for (int o = 16; o; o >>= 1) s += __shfl_down_sync(0xffffffffu, s, o);
        if (threadIdx.x == 0) sM0 = s * (1.0f / (float)CHW);
    }
    __syncthreads();

    // out = Af*v + Bf*channel_mean + Cf on valid pixels, else 0
    float a  = sat[b] * 2.0f;
    float k  = con[b] + 0.5f;
    float Af = k * a;
    float Bf = k * (1.0f - a);
    float Cf = (1.0f - k) * sM0 + (br[b] - 0.5f);

    int txs = tx[b] - SHIFT;
    int tys = ty[b] - SHIFT;
    int cxv = cx[b], cyv = cy[b];
    int xlo = max(0, cxv - 64), xhi = min(HH - 1, cxv + 63);
    int ylo = max(0, cyv - 64), yhi = min(WW - 1, cyv + 63);

    int  sh       = h + txs;
    bool rowvalid = (sh >= 0) & (sh < HH);
    bool rowcut   = (h >= xlo) & (h <= xhi);
    int  sh_c     = min(max(sh, 0), HH - 1);          // safe address even when invalid

    const float* src = imgs + (size_t)b * CHW + (size_t)sh_c * WW;

    float o0[4], o1[4], o2[4];
    #pragma unroll
    for (int j = 0; j < 4; j++) {
        int  w  = w0 + j;
        int  sw = w + tys;
        bool valid = rowvalid & (sw >= 0) & (sw < WW)
                   & !(rowcut & (w >= ylo) & (w <= yhi));
        int sw_c = min(max(sw, 0), WW - 1);
        if (valid) {
            // last-use reads: evict-first so dying input frees L2 for the
            // concurrently-running reduce of the next chunk
            float v0 = __ldcs(src + sw_c);
            float v1 = __ldcs(src + HW + sw_c);
            float v2 = __ldcs(src + 2 * HW + sw_c);
            float m  = (v0 + v1 + v2) * (1.0f / 3.0f);
            float bm = fmaf(Bf, m, Cf);
            o0[j] = fmaf(Af, v0, bm);
            o1[j] = fmaf(Af, v1, bm);
            o2[j] = fmaf(Af, v2, bm);
        } else {
            o0[j] = 0.f; o1[j] = 0.f; o2[j] = 0.f;
        }
    }

    float* dst = out + (size_t)b * CHW + (size_t)h * WW + w0;
    __stcs((float4*)(dst),          make_float4(o0[0], o0[1], o0[2], o0[3]));
    __stcs((float4*)(dst + HW),     make_float4(o1[0], o1[1], o1[2], o1[3]));
    __stcs((float4*)(dst + 2 * HW), make_float4(o2[0], o2[1], o2[2], o2[3]));
}

// Combined kernel: first ntr*BPI blocks transform images [tbase, tbase+ntr),
// remaining blocks reduce images [rbase, rbase+nred). Blocks are independent;
// the inter-launch barrier provides the reduce->transform ordering.
__global__ void __launch_bounds__(256) fused_kernel(
    const float* __restrict__ imgs,
    const float* __restrict__ br,  const float* __restrict__ sat,
    const float* __restrict__ con, const int* __restrict__ tx,
    const int* __restrict__ ty,    const int* __restrict__ cx,
    const int* __restrict__ cy,    float* __restrict__ out,
    int tbase, int ntr, int rbase)
{
    int ntrblk = ntr * BPI;
    if ((int)blockIdx.x < ntrblk) {
        transform_role(imgs, br, sat, con, tx, ty, cx, cy, out,
                       tbase + blockIdx.x / BPI, blockIdx.x % BPI);
    } else {
        int rix = blockIdx.x - ntrblk;
        reduce_role(imgs, rbase + rix / RBLKS, rix % RBLKS);
    }
}

extern "C" void kernel_launch(void* const* d_in, const int* in_sizes, int n_in,
                              void* d_out, int out_size)
{
    const float* imgs = (const float*)d_in[0];
    const float* br   = (const float*)d_in[1];
    const float* sat  = (const float*)d_in[2];
    const float* con  = (const float*)d_in[3];
    const int*   tx   = (const int*)d_in[4];
    const int*   ty   = (const int*)d_in[5];
    const int*   cx   = (const int*)d_in[6];
    const int*   cy   = (const int*)d_in[7];
    float*       out  = (float*)d_out;

    // K0: reduce half 0                     (2048 blocks)
    fused_kernel<<<HALF * RBLKS, 256>>>(imgs, br, sat, con, tx, ty, cx, cy, out,
                                        /*tbase*/0, /*ntr*/0, /*rbase*/0);
    // K1: transform half 0 + reduce half 1  (4096 + 2048 blocks)
    fused_kernel<<<HALF * BPI + HALF * RBLKS, 256>>>(imgs, br, sat, con, tx, ty, cx, cy, out,
                                        /*tbase*/0, /*ntr*/HALF, /*rbase*/HALF);
    // K2: transform half 1                  (4096 blocks)
    fused_kernel<<<HALF * BPI, 256>>>(imgs, br, sat, con, tx, ty, cx, cy, out,
                                        /*tbase*/HALF, /*ntr*/HALF, /*rbase*/0);
}